// round 17
// baseline (speedup 1.0000x reference)
#include <cuda_runtime.h>
#include <cuda_bf16.h>

// Problem constants (fixed by the reference): B=256, T=2048, L=4, H=64, P=1.
#define BSZ   256
#define TLEN  2048
#define NLAY  4
#define HID   64
#define CHUNK 32          // timesteps per BSP iteration (= warp width)
#define NCH   (TLEN/CHUNK)

#define L2E   1.4426950408889634f   // log2(e)
#define FXS   524288.0f             // 2^19 fixed-point scale (folded into wr)
#define FXI   1.9073486328125e-6f   // 2^-19 descale (folded into wh / outputs)
#define MAGIC 12582912.0f           // 1.5 * 2^23 : float->int round trick
#define MAGICB 0x4B400000

typedef unsigned long long ull;     // packed f32x2

__device__ __forceinline__ float ex2(float x) {
    float r; asm("ex2.approx.ftz.f32 %0, %1;" : "=f"(r) : "f"(x)); return r;
}
__device__ __forceinline__ float rcpa(float x) {
    float r; asm("rcp.approx.ftz.f32 %0, %1;" : "=f"(r) : "f"(x)); return r;
}
__device__ __forceinline__ int redux_add(int v) {
    int r; asm volatile("redux.sync.add.s32 %0, %1, 0xffffffff;" : "=r"(r) : "r"(v));
    return r;
}
// ---- f32x2 packed ops (FFMA2/FMUL2/FADD2 — PTX-only on sm_103a) ----
__device__ __forceinline__ ull pk(float lo, float hi) {
    ull r; asm("mov.b64 %0, {%1, %2};" : "=l"(r) : "f"(lo), "f"(hi)); return r;
}
__device__ __forceinline__ void upk(float& lo, float& hi, ull v) {
    asm("mov.b64 {%0, %1}, %2;" : "=f"(lo), "=f"(hi) : "l"(v));
}
__device__ __forceinline__ ull fma2(ull a, ull b, ull c) {
    ull r; asm("fma.rn.f32x2 %0, %1, %2, %3;" : "=l"(r) : "l"(a), "l"(b), "l"(c)); return r;
}
__device__ __forceinline__ ull mul2(ull a, ull b) {
    ull r; asm("mul.rn.f32x2 %0, %1, %2;" : "=l"(r) : "l"(a), "l"(b)); return r;
}
__device__ __forceinline__ ull add2(ull a, ull b) {
    ull r; asm("add.rn.f32x2 %0, %1, %2;" : "=l"(r) : "l"(a), "l"(b)); return r;
}

// Dual-batch BSP wavefront. Grid = B/2 blocks (<=148 -> 1 block/SM), block = 4
// warps; warp l runs layer l for BOTH batch elements (2*blk, 2*blk+1) as two
// independent interleaved chains sharing one register weight set -> exactly
// 1 warp/SMSP chip-wide, chain B fills chain A's latency bubbles.
// Per chain: lane ln owns cells {ln, ln+32}, packed f32x2 (part0,part1).
// Weights pre-scaled so gate FMA2 yields the EX2 argument directly:
//   sigm gates (i,f,o): a=-L2E*g -> sigm=1/(1+2^a); tanh g: a=-2L2E*g.
// Vertical Montgomery tree (2 rcp) + packed tanh(c) (2 rcp).
// Fixed-point h (2^19) + magic-number round + redux.sync.add.s32 allreduce.
__global__ __launch_bounds__(128) void lstm_db_kernel(
    const float* __restrict__ y,     // [B, T, 1]
    const float* __restrict__ Wih,   // [L, 256, 1]
    const float* __restrict__ Whh,   // [L, 256, 1]
    const float* __restrict__ bih,   // [L, 256]
    const float* __restrict__ bhh,   // [L, 256]
    const float* __restrict__ Whr,   // [L, 1, 64]
    const int*   __restrict__ mslp,
    float*       __restrict__ out)   // [B, T-msl, 1]
{
    __shared__ float ring_s[2][NLAY - 1][2][CHUNK];  // [chain][boundary][buf][lane]

    const int blk = blockIdx.x;
    const int l   = threadIdx.x >> 5;   // layer == warp id (one per SMSP)
    const int ln  = threadIdx.x & 31;
    const int b0  = 2 * blk, b1 = 2 * blk + 1;

    // ---- packed per-lane weights (shared by both chains) ----
    ull wi2[4], wh2[4], bs2[4];
    {
        const float* wih_l = Wih + l * 4 * HID;
        const float* whh_l = Whh + l * 4 * HID;
        const float* bih_l = bih + l * 4 * HID;
        const float* bhh_l = bhh + l * 4 * HID;
#pragma unroll
        for (int g = 0; g < 4; ++g) {           // 0:i 1:f 2:g 3:o
            float s = (g == 2) ? (-2.0f * L2E) : (-L2E);
            int i0 = g * 64 + ln, i1 = i0 + 32;
            wi2[g] = pk(s * wih_l[i0], s * wih_l[i1]);
            wh2[g] = pk(s * whh_l[i0] * FXI, s * whh_l[i1] * FXI); // eats int-valued h
            bs2[g] = pk(s * (bih_l[i0] + bhh_l[i0]), s * (bih_l[i1] + bhh_l[i1]));
        }
    }
    const ull wr2 = pk(Whr[l * HID + ln] * FXS, Whr[l * HID + ln + 32] * FXS);

    const ull ones2 = pk(1.0f, 1.0f);
    const ull neg12 = pk(-1.0f, -1.0f);
    const ull nl2e2 = pk(-2.0f * L2E, -2.0f * L2E);

    const int   msl = *mslp;
    const int   To  = TLEN - msl;
    const float* ybA = y + b0 * TLEN;
    const float* ybB = y + b1 * TLEN;

    float hfA = 0.0f, hfB = 0.0f;           // integer-valued floats (h * 2^19)
    ull cA = pk(0.0f, 0.0f), cB = pk(0.0f, 0.0f);
    float xpreA = (l == 0) ? ybA[ln] : 0.0f;
    float xpreB = (l == 0) ? ybB[ln] : 0.0f;

    const int NIT = NCH + NLAY - 1;          // 67 wavefront iterations
    for (int it = 0; it < NIT; ++it) {
        const int nc  = it - l;
        const bool act = ((unsigned)nc < (unsigned)NCH);

        if (act) {
            // ---- obtain input chunks (real scale) ----
            float xcurA, xcurB;
            if (l == 0) {
                xcurA = xpreA; xcurB = xpreB;
                if (nc + 1 < NCH) {
                    xpreA = ybA[(nc + 1) * CHUNK + ln];   // off-chain prefetch
                    xpreB = ybB[(nc + 1) * CHUNK + ln];
                }
            } else {
                xcurA = ring_s[0][l - 1][(it - 1) & 1][ln];
                xcurB = ring_s[1][l - 1][(it - 1) & 1][ln];
            }

            float keepA = 0.0f, keepB = 0.0f;
#pragma unroll 8
            for (int tt = 0; tt < CHUNK; ++tt) {
                float xa = __shfl_sync(0xffffffffu, xcurA, tt);
                float xb = __shfl_sync(0xffffffffu, xcurB, tt);
                ull xa2 = pk(xa, xa),   xb2 = pk(xb, xb);
                ull hA2 = pk(hfA, hfA), hB2 = pk(hfB, hfB);

                // ---- stage 1: gate args + ex2 + denominators, A then B ----
                ull eA[4], dA[4], eB[4], dB[4];
#pragma unroll
                for (int g = 0; g < 4; ++g) {
                    ull a2 = fma2(hA2, wh2[g], fma2(xa2, wi2[g], bs2[g]));
                    float a0, a1; upk(a0, a1, a2);
                    a0 = fminf(a0, 28.0f); a1 = fminf(a1, 28.0f);
                    eA[g] = pk(ex2(a0), ex2(a1));
                    dA[g] = add2(eA[g], ones2);
                }
#pragma unroll
                for (int g = 0; g < 4; ++g) {
                    ull a2 = fma2(hB2, wh2[g], fma2(xb2, wi2[g], bs2[g]));
                    float a0, a1; upk(a0, a1, a2);
                    a0 = fminf(a0, 28.0f); a1 = fminf(a1, 28.0f);
                    eB[g] = pk(ex2(a0), ex2(a1));
                    dB[g] = add2(eB[g], ones2);
                }

                // ---- stage 2: vertical Montgomery trees ----
                ull m1A = mul2(dA[0], dA[1]), m2A = mul2(dA[2], dA[3]);
                ull m3A = mul2(m1A, m2A);
                ull m1B = mul2(dB[0], dB[1]), m2B = mul2(dB[2], dB[3]);
                ull m3B = mul2(m1B, m2B);
                float PA0, PA1, PB0, PB1;
                upk(PA0, PA1, m3A); upk(PB0, PB1, m3B);
                ull rA2 = pk(rcpa(PA0), rcpa(PA1));
                ull rB2 = pk(rcpa(PB0), rcpa(PB1));
                ull tA = mul2(rA2, m2A), uA = mul2(rA2, m1A);
                ull tB = mul2(rB2, m2B), uB = mul2(rB2, m1B);
                ull giA = mul2(tA, dA[1]), gfA = mul2(tA, dA[0]);
                ull vgA = mul2(uA, dA[3]), goA = mul2(uA, dA[2]);
                ull giB = mul2(tB, dB[1]), gfB = mul2(tB, dB[0]);
                ull vgB = mul2(uB, dB[3]), goB = mul2(uB, dB[2]);

                ull tgA = mul2(fma2(eA[2], neg12, ones2), vgA);  // tanh(g)
                ull tgB = mul2(fma2(eB[2], neg12, ones2), vgB);

                // ---- stage 3: cell updates ----
                cA = fma2(gfA, cA, mul2(giA, tgA));
                cB = fma2(gfB, cB, mul2(giB, tgB));

                ull owA = mul2(goA, wr2);           // off-chain vs tanh(c)
                ull owB = mul2(goB, wr2);

                // ---- stage 4: tanh(c) ----
                ull acA = mul2(cA, nl2e2), acB = mul2(cB, nl2e2);
                float aA0, aA1, aB0, aB1;
                upk(aA0, aA1, acA); upk(aB0, aB1, acB);
                aA0 = fminf(aA0, 28.0f); aA1 = fminf(aA1, 28.0f);
                aB0 = fminf(aB0, 28.0f); aB1 = fminf(aB1, 28.0f);
                ull ecA = pk(ex2(aA0), ex2(aA1));
                ull ecB = pk(ex2(aB0), ex2(aB1));
                ull dcA = add2(ecA, ones2), dcB = add2(ecB, ones2);
                float qA0, qA1, qB0, qB1;
                upk(qA0, qA1, dcA); upk(qB0, qB1, dcB);
                ull rcA = pk(rcpa(qA0), rcpa(qA1));
                ull rcB = pk(rcpa(qB0), rcpa(qB1));
                ull tcA = mul2(fma2(ecA, neg12, ones2), rcA);
                ull tcB = mul2(fma2(ecB, neg12, ones2), rcB);

                // ---- stage 5: projection + fixed-point allreduce (pipelined) ----
                ull ptA = mul2(owA, tcA), ptB = mul2(owB, tcB);
                float pA0, pA1, pB0, pB1;
                upk(pA0, pA1, ptA); upk(pB0, pB1, ptB);
                float fmA = (pA0 + pA1) + MAGIC;
                float fmB = (pB0 + pB1) + MAGIC;
                int sA = redux_add(__float_as_int(fmA) - MAGICB);
                int sB = redux_add(__float_as_int(fmB) - MAGICB);
                hfA = __int_as_float(sA + MAGICB) - MAGIC;
                hfB = __int_as_float(sB + MAGICB) - MAGIC;

                keepA = (tt == ln) ? hfA : keepA;
                keepB = (tt == ln) ? hfB : keepB;
            }

            // ---- publish chunks (back to real scale once per chunk) ----
            if (l < NLAY - 1) {
                ring_s[0][l][it & 1][ln] = keepA * FXI;
                ring_s[1][l][it & 1][ln] = keepB * FXI;
            } else {
                int t = nc * CHUNK + ln;
                if (t >= msl) {
                    out[b0 * To + (t - msl)] = keepA * FXI;
                    out[b1 * To + (t - msl)] = keepB * FXI;
                }
            }
        }

        __syncthreads();   // single barrier: RAW + WAR for the double buffers
    }
}

extern "C" void kernel_launch(void* const* d_in, const int* in_sizes, int n_in,
                              void* d_out, int out_size) {
    const float* y    = (const float*)d_in[0];
    const float* Wih  = (const float*)d_in[1];
    const float* Whh  = (const float*)d_in[2];
    const float* bih  = (const float*)d_in[3];
    const float* bhh  = (const float*)d_in[4];
    const float* Whr  = (const float*)d_in[5];
    const int*   msl  = (const int*)  d_in[6];
    float* out = (float*)d_out;
    (void)in_sizes; (void)n_in; (void)out_size;

    lstm_db_kernel<<<BSZ / 2, 128>>>(y, Wih, Whh, bih, bhh, Whr, msl, out);
}